// round 6
// baseline (speedup 1.0000x reference)
#include <cuda_runtime.h>
#include <cuda_fp16.h>
#include <cstdint>

// Problem constants
#define BATCH   16384
#define MAXF    32
#define NFEAT   768
#define FT_OUT  1024

#define FULL_MASK 0xFFFFFFFFu

// fp16 copy of ft_w, rebuilt every kernel_launch (deterministic).
// 768*1024*2 = 1.5 MB — L2-resident during the main kernel.
__device__ __half g_ftw_h[NFEAT * FT_OUT];

// ---------------------------------------------------------------------------
// Kernel 1: convert ft_w fp32 -> fp16 (one float4 per thread)
// ---------------------------------------------------------------------------
__global__ void convert_ftw_kernel(const float* __restrict__ ftw) {
    int i = blockIdx.x * blockDim.x + threadIdx.x;
    float4 v = reinterpret_cast<const float4*>(ftw)[i];
    __half2* dst = reinterpret_cast<__half2*>(g_ftw_h);
    dst[2 * i + 0] = __floats2half2_rn(v.x, v.y);
    dst[2 * i + 1] = __floats2half2_rn(v.z, v.w);
}

// ---------------------------------------------------------------------------
// Kernel 2: FOUR warps per sample (each owns 256 of 1024 columns),
// stm/nstm fused -> 2 independent LDG.128 per feature iteration.
// Per feature per warp: 2x LDG.128 + 8x HFMA2 + 3x SHFL.
// __launch_bounds__(256,5): <=51 regs -> 5 CTAs/SM = 40 warps (62.5% occ).
// ---------------------------------------------------------------------------
__global__ void __launch_bounds__(256, 5)
nnue_main_kernel(const float* __restrict__ values,
                 const int*   __restrict__ stm_idx,
                 const int*   __restrict__ nstm_idx,
                 const float* __restrict__ ft_b,
                 const float* __restrict__ out_w,
                 const float* __restrict__ out_b,
                 float*       __restrict__ out)
{
    __shared__ float s_partial[8];   // one slot per warp in CTA

    const int warpInCta = threadIdx.x >> 5;
    const int lane      = threadIdx.x & 31;
    const int gwarp     = blockIdx.x * 8 + warpInCta;
    const int b         = gwarp >> 2;        // sample (2 samples per CTA)
    const int q         = gwarp & 3;         // column quarter: 0..3
    // 16384*4 warps exactly fill 8192 CTAs; no bounds check needed.

    // Each lane caches one feature's ROW BYTE OFFSET (both sides) and value.
    const int   offS  = stm_idx [b * MAXF + lane] * (FT_OUT * 2);
    const int   offN  = nstm_idx[b * MAXF + lane] * (FT_OUT * 2);
    const float my_val = values  [b * MAXF + lane];

    // Per-lane base: quarter offset + lane's 16B chunk within the quarter.
    const char* Wq = reinterpret_cast<const char*>(g_ftw_h) + q * 512 + lane * 16;

    // Accumulators: 4 half2 per side (256 cols / 32 lanes / 2 per half2)
    __half2 accS[4], accN[4];
    #pragma unroll
    for (int i = 0; i < 4; ++i) {
        accS[i] = __half2half2(__float2half_rn(0.0f));
        accN[i] = accS[i];
    }

    #pragma unroll 4
    for (int f = 0; f < MAXF; ++f) {
        const int   oS = __shfl_sync(FULL_MASK, offS,   f);
        const int   oN = __shfl_sync(FULL_MASK, offN,   f);
        const float v  = __shfl_sync(FULL_MASK, my_val, f);
        const __half2 v2 = __float2half2_rn(v);

        uint4 ds = *reinterpret_cast<const uint4*>(Wq + oS);
        uint4 dn = *reinterpret_cast<const uint4*>(Wq + oN);

        accS[0] = __hfma2(v2, *reinterpret_cast<__half2*>(&ds.x), accS[0]);
        accS[1] = __hfma2(v2, *reinterpret_cast<__half2*>(&ds.y), accS[1]);
        accS[2] = __hfma2(v2, *reinterpret_cast<__half2*>(&ds.z), accS[2]);
        accS[3] = __hfma2(v2, *reinterpret_cast<__half2*>(&ds.w), accS[3]);
        accN[0] = __hfma2(v2, *reinterpret_cast<__half2*>(&dn.x), accN[0]);
        accN[1] = __hfma2(v2, *reinterpret_cast<__half2*>(&dn.y), accN[1]);
        accN[2] = __hfma2(v2, *reinterpret_cast<__half2*>(&dn.z), accN[2]);
        accN[3] = __hfma2(v2, *reinterpret_cast<__half2*>(&dn.w), accN[3]);
    }

    // ----- epilogue: fp32 bias add, clip [0,1], dot with out_w -----
    // Lane's 8 columns per side start at col0 = q*256 + lane*8
    //   -> float4 indices fidx = q*64 + lane*2 + {0,1}
    const float4* fb4 = reinterpret_cast<const float4*>(ft_b);
    const float4* ow4 = reinterpret_cast<const float4*>(out_w);
    const int fidx = q * 64 + lane * 2;

    float partial = 0.0f;
    {
        float4 b0 = fb4[fidx + 0];
        float4 b1 = fb4[fidx + 1];
        #pragma unroll
        for (int side = 0; side < 2; ++side) {
            const __half2* acc = (side == 0) ? accS : accN;
            const int owb = side * 256 + fidx;   // +256 float4 = +1024 cols
            float4 w0 = ow4[owb + 0];
            float4 w1 = ow4[owb + 1];
            float2 p0 = __half22float2(acc[0]);
            float2 p1 = __half22float2(acc[1]);
            float2 p2 = __half22float2(acc[2]);
            float2 p3 = __half22float2(acc[3]);
            float hh;
            hh = fminf(fmaxf(p0.x + b0.x, 0.f), 1.f); partial = fmaf(hh, w0.x, partial);
            hh = fminf(fmaxf(p0.y + b0.y, 0.f), 1.f); partial = fmaf(hh, w0.y, partial);
            hh = fminf(fmaxf(p1.x + b0.z, 0.f), 1.f); partial = fmaf(hh, w0.z, partial);
            hh = fminf(fmaxf(p1.y + b0.w, 0.f), 1.f); partial = fmaf(hh, w0.w, partial);
            hh = fminf(fmaxf(p2.x + b1.x, 0.f), 1.f); partial = fmaf(hh, w1.x, partial);
            hh = fminf(fmaxf(p2.y + b1.y, 0.f), 1.f); partial = fmaf(hh, w1.y, partial);
            hh = fminf(fmaxf(p3.x + b1.z, 0.f), 1.f); partial = fmaf(hh, w1.z, partial);
            hh = fminf(fmaxf(p3.y + b1.w, 0.f), 1.f); partial = fmaf(hh, w1.w, partial);
        }
    }

    // warp reduce
    #pragma unroll
    for (int off = 16; off > 0; off >>= 1)
        partial += __shfl_xor_sync(FULL_MASK, partial, off);

    if (lane == 0) s_partial[warpInCta] = partial;
    __syncthreads();

    // quarter-0 warp of each sample finalizes
    if ((warpInCta & 3) == 0 && lane == 0) {
        float x = s_partial[warpInCta]     + s_partial[warpInCta + 1]
                + s_partial[warpInCta + 2] + s_partial[warpInCta + 3]
                + out_b[0];
        out[b] = 1.0f / (1.0f + __expf(-x));
    }
}

// ---------------------------------------------------------------------------
// kernel_launch
// Input order (metadata): values, stm_indices, nstm_indices, ft_w, ft_b, out_w, out_b
// Output: float32 [16384]
// ---------------------------------------------------------------------------
extern "C" void kernel_launch(void* const* d_in, const int* in_sizes, int n_in,
                              void* d_out, int out_size)
{
    const float* values   = (const float*)d_in[0];
    const int*   stm_idx  = (const int*)  d_in[1];
    const int*   nstm_idx = (const int*)  d_in[2];
    const float* ft_w     = (const float*)d_in[3];
    const float* ft_b     = (const float*)d_in[4];
    const float* out_w    = (const float*)d_in[5];
    const float* out_b    = (const float*)d_in[6];
    float*       out      = (float*)d_out;

    // 1) ft_w fp32 -> fp16  (768*1024/4 = 196608 threads)
    convert_ftw_kernel<<<(NFEAT * FT_OUT / 4 + 255) / 256, 256>>>(ft_w);

    // 2) main: four warps per sample, 8 warps per CTA -> 8192 CTAs
    const int grid = BATCH * 4 / 8;
    nnue_main_kernel<<<grid, 256>>>(values, stm_idx, nstm_idx,
                                    ft_b, out_w, out_b, out);
}

// round 7
// speedup vs baseline: 1.0615x; 1.0615x over previous
#include <cuda_runtime.h>
#include <cuda_fp16.h>
#include <cstdint>

// Problem constants
#define BATCH   16384
#define MAXF    32
#define NFEAT   768
#define FT_OUT  1024

#define FULL_MASK 0xFFFFFFFFu

// fp16 copy of ft_w, rebuilt every kernel_launch (deterministic).
// 768*1024*2 = 1.5 MB — L2-resident during the main kernel.
__device__ __half g_ftw_h[NFEAT * FT_OUT];

// ---------------------------------------------------------------------------
// Kernel 1: convert ft_w fp32 -> fp16 (one float4 per thread)
// ---------------------------------------------------------------------------
__global__ void convert_ftw_kernel(const float* __restrict__ ftw) {
    int i = blockIdx.x * blockDim.x + threadIdx.x;
    float4 v = reinterpret_cast<const float4*>(ftw)[i];
    __half2* dst = reinterpret_cast<__half2*>(g_ftw_h);
    dst[2 * i + 0] = __floats2half2_rn(v.x, v.y);
    dst[2 * i + 1] = __floats2half2_rn(v.z, v.w);
}

// ---------------------------------------------------------------------------
// Kernel 2: FOUR warps per sample (each owns 256 of 1024 columns).
// Per-feature metadata staged in smem ONCE, then broadcast via a single
// uniform LDS.64 per feature (replaces 3 SHFLs -> fewer crossbar ops).
// Per feature per warp: 1 LDS.64 + 2 LDG.128 + 8 HFMA2 + index ALU.
// ---------------------------------------------------------------------------
__global__ void __launch_bounds__(256, 5)
nnue_main_kernel(const float* __restrict__ values,
                 const int*   __restrict__ stm_idx,
                 const int*   __restrict__ nstm_idx,
                 const float* __restrict__ ft_b,
                 const float* __restrict__ out_w,
                 const float* __restrict__ out_b,
                 float*       __restrict__ out)
{
    __shared__ uint2 s_meta[2][MAXF];   // [sampleInCta][feature] = {idxS|idxN<<16, valbits}
    __shared__ float s_partial[8];      // one slot per warp

    const int tid       = threadIdx.x;
    const int warpInCta = tid >> 5;
    const int lane      = tid & 31;
    const int sInCta    = warpInCta >> 2;     // 2 samples per CTA
    const int q         = warpInCta & 3;      // column quarter 0..3
    const int b         = blockIdx.x * 2 + sInCta;

    // Stage metadata: threads 0..63 each handle one (sample, feature)
    if (tid < 64) {
        const int s = tid >> 5;
        const int f = tid & 31;
        const int bg = blockIdx.x * 2 + s;
        const int is = stm_idx [bg * MAXF + f];
        const int in = nstm_idx[bg * MAXF + f];
        const float v = values [bg * MAXF + f];
        s_meta[s][f] = make_uint2((unsigned)is | ((unsigned)in << 16),
                                  __float_as_uint(v));
    }
    __syncthreads();

    // Per-lane base: quarter offset + lane's 16B chunk within the quarter.
    const char* Wq = reinterpret_cast<const char*>(g_ftw_h) + q * 512 + lane * 16;

    // Accumulators: 4 half2 per side (256 cols / 32 lanes / 2 per half2)
    __half2 accS[4], accN[4];
    #pragma unroll
    for (int i = 0; i < 4; ++i) {
        accS[i] = __half2half2(__float2half_rn(0.0f));
        accN[i] = accS[i];
    }

    #pragma unroll 8
    for (int f = 0; f < MAXF; ++f) {
        const uint2 m = s_meta[sInCta][f];          // uniform LDS.64 broadcast
        const unsigned idxS =  m.x & 0xFFFFu;
        const unsigned idxN =  m.x >> 16;
        const __half2 v2 = __float2half2_rn(__uint_as_float(m.y));

        uint4 ds = *reinterpret_cast<const uint4*>(Wq + (size_t)idxS * (FT_OUT * 2));
        uint4 dn = *reinterpret_cast<const uint4*>(Wq + (size_t)idxN * (FT_OUT * 2));

        accS[0] = __hfma2(v2, *reinterpret_cast<__half2*>(&ds.x), accS[0]);
        accS[1] = __hfma2(v2, *reinterpret_cast<__half2*>(&ds.y), accS[1]);
        accS[2] = __hfma2(v2, *reinterpret_cast<__half2*>(&ds.z), accS[2]);
        accS[3] = __hfma2(v2, *reinterpret_cast<__half2*>(&ds.w), accS[3]);
        accN[0] = __hfma2(v2, *reinterpret_cast<__half2*>(&dn.x), accN[0]);
        accN[1] = __hfma2(v2, *reinterpret_cast<__half2*>(&dn.y), accN[1]);
        accN[2] = __hfma2(v2, *reinterpret_cast<__half2*>(&dn.z), accN[2]);
        accN[3] = __hfma2(v2, *reinterpret_cast<__half2*>(&dn.w), accN[3]);
    }

    // ----- epilogue: fp32 bias add, clip [0,1], dot with out_w -----
    // Lane's 8 columns per side start at col0 = q*256 + lane*8
    //   -> float4 indices fidx = q*64 + lane*2 + {0,1}
    const float4* fb4 = reinterpret_cast<const float4*>(ft_b);
    const float4* ow4 = reinterpret_cast<const float4*>(out_w);
    const int fidx = q * 64 + lane * 2;

    float partial = 0.0f;
    {
        float4 b0 = fb4[fidx + 0];
        float4 b1 = fb4[fidx + 1];
        #pragma unroll
        for (int side = 0; side < 2; ++side) {
            const __half2* acc = (side == 0) ? accS : accN;
            const int owb = side * 256 + fidx;   // +256 float4 = +1024 cols
            float4 w0 = ow4[owb + 0];
            float4 w1 = ow4[owb + 1];
            float2 p0 = __half22float2(acc[0]);
            float2 p1 = __half22float2(acc[1]);
            float2 p2 = __half22float2(acc[2]);
            float2 p3 = __half22float2(acc[3]);
            float hh;
            hh = fminf(fmaxf(p0.x + b0.x, 0.f), 1.f); partial = fmaf(hh, w0.x, partial);
            hh = fminf(fmaxf(p0.y + b0.y, 0.f), 1.f); partial = fmaf(hh, w0.y, partial);
            hh = fminf(fmaxf(p1.x + b0.z, 0.f), 1.f); partial = fmaf(hh, w0.z, partial);
            hh = fminf(fmaxf(p1.y + b0.w, 0.f), 1.f); partial = fmaf(hh, w0.w, partial);
            hh = fminf(fmaxf(p2.x + b1.x, 0.f), 1.f); partial = fmaf(hh, w1.x, partial);
            hh = fminf(fmaxf(p2.y + b1.y, 0.f), 1.f); partial = fmaf(hh, w1.y, partial);
            hh = fminf(fmaxf(p3.x + b1.z, 0.f), 1.f); partial = fmaf(hh, w1.z, partial);
            hh = fminf(fmaxf(p3.y + b1.w, 0.f), 1.f); partial = fmaf(hh, w1.w, partial);
        }
    }

    // warp reduce
    #pragma unroll
    for (int off = 16; off > 0; off >>= 1)
        partial += __shfl_xor_sync(FULL_MASK, partial, off);

    if (lane == 0) s_partial[warpInCta] = partial;
    __syncthreads();

    // quarter-0 warp of each sample finalizes
    if (q == 0 && lane == 0) {
        float x = s_partial[warpInCta]     + s_partial[warpInCta + 1]
                + s_partial[warpInCta + 2] + s_partial[warpInCta + 3]
                + out_b[0];
        out[b] = 1.0f / (1.0f + __expf(-x));
    }
}

// ---------------------------------------------------------------------------
// kernel_launch
// Input order (metadata): values, stm_indices, nstm_indices, ft_w, ft_b, out_w, out_b
// Output: float32 [16384]
// ---------------------------------------------------------------------------
extern "C" void kernel_launch(void* const* d_in, const int* in_sizes, int n_in,
                              void* d_out, int out_size)
{
    const float* values   = (const float*)d_in[0];
    const int*   stm_idx  = (const int*)  d_in[1];
    const int*   nstm_idx = (const int*)  d_in[2];
    const float* ft_w     = (const float*)d_in[3];
    const float* ft_b     = (const float*)d_in[4];
    const float* out_w    = (const float*)d_in[5];
    const float* out_b    = (const float*)d_in[6];
    float*       out      = (float*)d_out;

    // 1) ft_w fp32 -> fp16  (768*1024/4 = 196608 threads)
    convert_ftw_kernel<<<(NFEAT * FT_OUT / 4 + 255) / 256, 256>>>(ft_w);

    // 2) main: four warps per sample, 8 warps per CTA -> 8192 CTAs
    nnue_main_kernel<<<BATCH / 2, 256>>>(values, stm_idx, nstm_idx,
                                         ft_b, out_w, out_b, out);
}